// round 6
// baseline (speedup 1.0000x reference)
#include <cuda_runtime.h>
#include <cstdint>

typedef unsigned long long u64;
typedef unsigned int u32;

// ---------------- device scratch (no allocations allowed) ----------------
__device__ float g_part_edge[160][64];
__device__ float g_part_node[160][64];
__device__ float g_zhist[64];
__device__ float g_base[64];
__device__ float g_av[64];
__device__ float g_bv[64];
__device__ float g_w2v[64];

// ---------------- packed helpers ------------------------------------------
__device__ __forceinline__ u64 pk2(float a, float b) {
    u64 r; asm("mov.b64 %0,{%1,%2};" : "=l"(r) : "f"(a), "f"(b)); return r;
}
__device__ __forceinline__ void up2(u64 v, float& a, float& b) {
    asm("mov.b64 {%0,%1},%2;" : "=f"(a), "=f"(b) : "l"(v));
}
__device__ __forceinline__ u64 f2fma(u64 a, u64 b, u64 c) {
    u64 d; asm("fma.rn.f32x2 %0,%1,%2,%3;" : "=l"(d) : "l"(a), "l"(b), "l"(c)); return d;
}
__device__ __forceinline__ u64 add2(u64 a, u64 b) {
    u64 d; asm("add.rn.f32x2 %0,%1,%2;" : "=l"(d) : "l"(a), "l"(b)); return d;
}
__device__ __forceinline__ u64 relu2(u64 v) {
    u64 r;
    asm("{\n\t.reg .f32 l,h;\n\t"
        "mov.b64 {l,h}, %1;\n\t"
        "max.f32 l, l, 0f00000000;\n\t"
        "max.f32 h, h, 0f00000000;\n\t"
        "mov.b64 %0, {l,h};\n\t}"
        : "=l"(r) : "l"(v));
    return r;
}
__device__ __forceinline__ float tanh_ap(float x) {
    float r; asm("tanh.approx.f32 %0,%1;" : "=f"(r) : "f"(x)); return r;
}
__device__ __forceinline__ float sigm(float x) { return 1.f / (1.f + __expf(-x)); }

__device__ __forceinline__ u32 bfpack(float lo, float hi) {
    u32 r; asm("cvt.rn.bf16x2.f32 %0, %1, %2;" : "=r"(r) : "f"(hi), "f"(lo)); return r;
}

__device__ __forceinline__ void mma8(float& d0, float& d1, float& d2, float& d3,
                                     u32 a0, u32 a1, u32 b,
                                     float c0, float c1, float c2, float c3) {
    asm("mma.sync.aligned.m16n8k8.row.col.f32.bf16.bf16.f32 "
        "{%0,%1,%2,%3},{%4,%5},{%6},{%7,%8,%9,%10};"
        : "=f"(d0), "=f"(d1), "=f"(d2), "=f"(d3)
        : "r"(a0), "r"(a1), "r"(b), "f"(c0), "f"(c1), "f"(c2), "f"(c3));
}

#define NTH   768
#define NW    24              // warps per block
#define CH    128             // rows per warp chunk
#define REDW  68

// ---- dynamic shared layout (bytes), union of two uses --------------------
//  phase:  scratch [0, 61440)      24 warps x 640 floats (f32 chunk)
//          red     [61440, 67968)  24*68 floats
//  LSTM :  whh     [0, 67584)      256 rows x 66 floats
//          hist    [67584, 70016)  608 floats
//          shg     [70016, 71040)  256 floats
//          shh     [71040, 71296)  64 floats
#define K1_SMEM 71296

extern __shared__ __align__(16) char dsm_raw[];

// ---------------- per-warp streaming tensor-core MLP reduction ------------
// Each warp independently streams 128-row chunks (contiguous, coalesced
// LDG.128 into registers -> warp-private shared scratch). No block syncs in
// the mainloop. mma m16n8k8 bf16; bias via C operand; relu+mean in f32x2.
template<int INF>
__device__ __forceinline__ void phase(const float* __restrict__ X,
                                      const float* __restrict__ W,
                                      const float* __restrict__ bias,
                                      int nrows, float* __restrict__ partial,
                                      int nstreams, int ws)
{
    const int tid  = threadIdx.x;
    const int lane = tid & 31;
    const int w    = tid >> 5;
    const int gid  = lane >> 2;      // 0..7
    const int tig  = lane & 3;       // 0..3
    float* sw  = (float*)dsm_raw + w * 640;
    float* red = (float*)(dsm_raw + 61440);

    // B fragments (col = nt*8+gid, k = 2tig,2tig+1) + bias C (cols nt*8+2tig..+1)
    u32 bf[8];
    float c0[8], c1[8];
#pragma unroll
    for (int nt = 0; nt < 8; nt++) {
        const int ncol = nt * 8 + gid;
        const float vlo = (2 * tig < INF)     ? W[(2 * tig) * 64 + ncol]     : 0.f;
        const float vhi = (2 * tig + 1 < INF) ? W[(2 * tig + 1) * 64 + ncol] : 0.f;
        bf[nt] = bfpack(vlo, vhi);
        c0[nt] = bias[nt * 8 + 2 * tig];
        c1[nt] = bias[nt * 8 + 2 * tig + 1];
    }
    u64 acc[8] = {0, 0, 0, 0, 0, 0, 0, 0};

    const int nch = (nrows + CH - 1) / CH;
    const int nelem = nrows * INF;
    constexpr int NV = (CH * INF) / 128;    // float4 per lane per chunk
    float4 pf[NV];

    __syncthreads();   // protect scratch/red across phases

    int c = ws;
    if (c < nch) {
        const int b4 = c * (CH * INF / 4);
        if ((c + 1) * CH <= nrows) {
#pragma unroll
            for (int v = 0; v < NV; v++) pf[v] = ((const float4*)X)[b4 + lane + v * 32];
        } else {
#pragma unroll
            for (int v = 0; v < NV; v++) {
                const int e = (b4 + lane + v * 32) * 4;
                pf[v].x = (e     < nelem) ? X[e]     : 0.f;
                pf[v].y = (e + 1 < nelem) ? X[e + 1] : 0.f;
                pf[v].z = (e + 2 < nelem) ? X[e + 2] : 0.f;
                pf[v].w = (e + 3 < nelem) ? X[e + 3] : 0.f;
            }
        }
    }

    for (; c < nch; c += nstreams) {
#pragma unroll
        for (int v = 0; v < NV; v++) ((float4*)sw)[lane + v * 32] = pf[v];
        __syncwarp();

        const int cn = c + nstreams;
        if (cn < nch) {
            const int b4 = cn * (CH * INF / 4);
            if ((cn + 1) * CH <= nrows) {
#pragma unroll
                for (int v = 0; v < NV; v++) pf[v] = ((const float4*)X)[b4 + lane + v * 32];
            } else {
#pragma unroll
                for (int v = 0; v < NV; v++) {
                    const int e = (b4 + lane + v * 32) * 4;
                    pf[v].x = (e     < nelem) ? X[e]     : 0.f;
                    pf[v].y = (e + 1 < nelem) ? X[e + 1] : 0.f;
                    pf[v].z = (e + 2 < nelem) ? X[e + 2] : 0.f;
                    pf[v].w = (e + 3 < nelem) ? X[e + 3] : 0.f;
                }
            }
        }

        const int rows = min(CH, nrows - c * CH);
        if (rows == CH) {
#pragma unroll
            for (int t = 0; t < 8; t++) {
                const int r0 = t * 16 + gid;
                const float lo0 = (2 * tig < INF)     ? sw[r0 * INF + 2 * tig]           : 0.f;
                const float hi0 = (2 * tig + 1 < INF) ? sw[r0 * INF + 2 * tig + 1]       : 0.f;
                const float lo1 = (2 * tig < INF)     ? sw[(r0 + 8) * INF + 2 * tig]     : 0.f;
                const float hi1 = (2 * tig + 1 < INF) ? sw[(r0 + 8) * INF + 2 * tig + 1] : 0.f;
                const u32 a0 = bfpack(lo0, hi0);
                const u32 a1 = bfpack(lo1, hi1);
#pragma unroll
                for (int nt = 0; nt < 8; nt++) {
                    float d0, d1, d2, d3;
                    mma8(d0, d1, d2, d3, a0, a1, bf[nt], c0[nt], c1[nt], c0[nt], c1[nt]);
                    acc[nt] = add2(relu2(pk2(d0, d1)), acc[nt]);
                    acc[nt] = add2(relu2(pk2(d2, d3)), acc[nt]);
                }
            }
        } else {
#pragma unroll
            for (int t = 0; t < 8; t++) {
                const int r0 = t * 16 + gid;
                const float lo0 = (2 * tig < INF)     ? sw[r0 * INF + 2 * tig]           : 0.f;
                const float hi0 = (2 * tig + 1 < INF) ? sw[r0 * INF + 2 * tig + 1]       : 0.f;
                const float lo1 = (2 * tig < INF)     ? sw[(r0 + 8) * INF + 2 * tig]     : 0.f;
                const float hi1 = (2 * tig + 1 < INF) ? sw[(r0 + 8) * INF + 2 * tig + 1] : 0.f;
                const u32 a0 = bfpack(lo0, hi0);
                const u32 a1 = bfpack(lo1, hi1);
                const float m0 = (r0 < rows) ? 1.f : 0.f;
                const float m1 = (r0 + 8 < rows) ? 1.f : 0.f;
                const u64 m0p = pk2(m0, m0);
                const u64 m1p = pk2(m1, m1);
#pragma unroll
                for (int nt = 0; nt < 8; nt++) {
                    float d0, d1, d2, d3;
                    mma8(d0, d1, d2, d3, a0, a1, bf[nt], c0[nt], c1[nt], c0[nt], c1[nt]);
                    acc[nt] = f2fma(relu2(pk2(d0, d1)), m0p, acc[nt]);
                    acc[nt] = f2fma(relu2(pk2(d2, d3)), m1p, acc[nt]);
                }
            }
        }
        __syncwarp();
    }

    // reduce over gid (shfl xor 4,8,16), then cross-warp via shared
    __syncthreads();
#pragma unroll
    for (int nt = 0; nt < 8; nt++) {
        float lo, hi; up2(acc[nt], lo, hi);
#pragma unroll
        for (int off = 4; off <= 16; off <<= 1) {
            lo += __shfl_xor_sync(0xffffffffu, lo, off);
            hi += __shfl_xor_sync(0xffffffffu, hi, off);
        }
        if (gid == 0) {
            red[w * REDW + nt * 8 + 2 * tig]     = lo;
            red[w * REDW + nt * 8 + 2 * tig + 1] = hi;
        }
    }
    __syncthreads();
    if (tid < 64) {
        float sum = 0.f;
#pragma unroll 8
        for (int r2 = 0; r2 < NW; r2++) sum += red[r2 * REDW + tid];
        partial[tid] = sum;
    }
}

// ---------------- kernel 1: LSTM (block 0) + node/edge reduce -------------
__global__ void __launch_bounds__(NTH, 1) k1(
    const float* __restrict__ node, const float* __restrict__ edge,
    const float* __restrict__ hist, int Nn, int Ne, int T,
    const float* __restrict__ nodeW, const float* __restrict__ nodeb,
    const float* __restrict__ edgeW, const float* __restrict__ edgeb,
    const float* __restrict__ Wih, const float* __restrict__ Whh,
    const float* __restrict__ bih, const float* __restrict__ bhh)
{
    const int tid = threadIdx.x;

    if (blockIdx.x == 0) {
        // ---------------- LSTM: Whh in shared, named barriers -------------
        float* whh_f   = (float*)dsm_raw;               // 256 x 66 floats
        float* sh_hist = (float*)(dsm_raw + 67584);
        float* sh_g    = (float*)(dsm_raw + 70016);
        float* sh_h    = (float*)(dsm_raw + 71040);

        for (int e = tid; e < 256 * 64; e += NTH) {
            const int r = e >> 6, kf = e & 63;
            whh_f[r * 66 + kf] = Whh[e];
        }
        for (int i = tid; i < T * 3 && i < 608; i += NTH) sh_hist[i] = hist[i];
        if (tid < 64) sh_h[tid] = 0.f;
        __syncthreads();

        if (tid < 256) {
            const float wi0 = Wih[tid * 3], wi1 = Wih[tid * 3 + 1], wi2 = Wih[tid * 3 + 2];
            const float bsum = bih[tid] + bhh[tid];
            const bool hsh = (T * 3 <= 608);
            const u64* wrow = (const u64*)whh_f + tid * 33;
            const bool is_tanh_gate = (tid >= 128 && tid < 192);
            float c = 0.f;

            for (int t = 0; t < T; t++) {
                const float* xp = hsh ? (sh_hist + t * 3) : (hist + t * 3);
                float pre = fmaf(wi0, xp[0], fmaf(wi1, xp[1], fmaf(wi2, xp[2], bsum)));
                const u64* hp = (const u64*)sh_h;
                u64 a0 = 0, a1 = 0, a2 = 0, a3 = 0;
#pragma unroll
                for (int k = 0; k < 32; k += 4) {
                    a0 = f2fma(wrow[k],     hp[k],     a0);
                    a1 = f2fma(wrow[k + 1], hp[k + 1], a1);
                    a2 = f2fma(wrow[k + 2], hp[k + 2], a2);
                    a3 = f2fma(wrow[k + 3], hp[k + 3], a3);
                }
                float s0, s1, s2, s3, s4, s5, s6, s7;
                up2(a0, s0, s1); up2(a1, s2, s3); up2(a2, s4, s5); up2(a3, s6, s7);
                const float z = pre + ((s0 + s1) + (s2 + s3)) + ((s4 + s5) + (s6 + s7));
                sh_g[tid] = is_tanh_gate ? tanh_ap(z) : sigm(z);
                asm volatile("bar.sync 1, 256;" ::: "memory");
                if (tid < 64) {
                    const float ig = sh_g[tid], fg = sh_g[64 + tid];
                    const float gg = sh_g[128 + tid], og = sh_g[192 + tid];
                    c = fmaf(fg, c, ig * gg);
                    sh_h[tid] = og * tanh_ap(c);
                }
                asm volatile("bar.sync 1, 256;" ::: "memory");
            }
            if (tid < 64) g_zhist[tid] = sh_h[tid];
        }
    } else {
        const int nstreams = (gridDim.x - 1) * NW;
        const int ws = (blockIdx.x - 1) * NW + (tid >> 5);
        phase<2>(node, nodeW, nodeb, Nn, g_part_node[blockIdx.x - 1], nstreams, ws);
        phase<5>(edge, edgeW, edgeb, Ne, g_part_edge[blockIdx.x - 1], nstreams, ws);
    }
}

// ---------------- kernel 2: finalize ctx + precompute base/a/b/w2 ---------
__global__ void __launch_bounds__(256) k2(int nb, int Nn, int Ne,
                   const float* __restrict__ W1, const float* __restrict__ b1,
                   const float* __restrict__ W2f)
{
    __shared__ float ctx[192];
    __shared__ float t1[256], t2[256];
    const int tid = threadIdx.x;
    const int c = tid >> 6, j = tid & 63;

    float se = 0.f, sn = 0.f;
    for (int b = c; b < nb; b += 4) {
        se += g_part_edge[b][j];
        sn += g_part_node[b][j];
    }
    t1[tid] = se; t2[tid] = sn;
    __syncthreads();
    if (tid < 64) {
        const float e = t1[tid] + t1[tid + 64] + t1[tid + 128] + t1[tid + 192];
        const float n = t2[tid] + t2[tid + 64] + t2[tid + 128] + t2[tid + 192];
        ctx[tid]       = n * (1.f / (float)Nn);
        ctx[64 + tid]  = e * (1.f / (float)Ne);
        ctx[128 + tid] = g_zhist[tid];
    }
    __syncthreads();
    float p = 0.f;
    const int i0 = c * 48;
#pragma unroll 8
    for (int i = i0; i < i0 + 48; i++) p = fmaf(ctx[i], W1[i * 64 + j], p);
    __syncthreads();
    t1[tid] = p;
    __syncthreads();
    if (tid < 64) {
        g_base[tid] = b1[tid] + ((t1[tid] + t1[tid + 64]) + (t1[tid + 128] + t1[tid + 192]));
        g_av[tid]   = W1[192 * 64 + tid];
        g_bv[tid]   = W1[193 * 64 + tid];
        g_w2v[tid]  = W2f[tid];
    }
}

// ---------------- kernel 3: candidate scoring (ILP=8, shared wt reuse) ----
__global__ void __launch_bounds__(256) k3(const int* __restrict__ cand, int P,
                                          const int* __restrict__ Np,
                                          const float* __restrict__ fb2,
                                          float* __restrict__ out)
{
    __shared__ __align__(16) u64 s4[128];   // [jp]{base2, a2, b2, w22}
    const int tid = threadIdx.x;
    if (tid < 32) {
        s4[tid * 4 + 0] = pk2(g_base[2 * tid], g_base[2 * tid + 1]);
        s4[tid * 4 + 1] = pk2(g_av[2 * tid],   g_av[2 * tid + 1]);
        s4[tid * 4 + 2] = pk2(g_bv[2 * tid],   g_bv[2 * tid + 1]);
        s4[tid * 4 + 3] = pk2(g_w2v[2 * tid],  g_w2v[2 * tid + 1]);
    }
    const float invd = 1.f / ((float)(*Np) - 1.f + 1e-9f);
    const float bias2 = fb2[0];
    __syncthreads();

    const int p0 = blockIdx.x * 2048 + tid;
    u64 cx2[8], cy2[8];
#pragma unroll
    for (int i = 0; i < 8; i++) {
        const int p = p0 + i * 256;
        float cx = 0.f, cy = 0.f;
        if (p < P) {
            const int2 cp = ((const int2*)cand)[p];
            cx = (float)cp.x * invd;
            cy = (float)cp.y * invd;
        }
        cx2[i] = pk2(cx, cx);
        cy2[i] = pk2(cy, cy);
    }

    u64 acc[8] = {0, 0, 0, 0, 0, 0, 0, 0};
#pragma unroll 8
    for (int jp = 0; jp < 32; jp++) {
        const u64 bb = s4[jp * 4 + 0];
        const u64 aa = s4[jp * 4 + 1];
        const u64 bv = s4[jp * 4 + 2];
        const u64 ww = s4[jp * 4 + 3];
#pragma unroll
        for (int i = 0; i < 8; i++) {
            u64 tt = f2fma(cx2[i], aa, bb);
            tt = f2fma(cy2[i], bv, tt);
            acc[i] = f2fma(relu2(tt), ww, acc[i]);
        }
    }
#pragma unroll
    for (int i = 0; i < 8; i++) {
        const int p = p0 + i * 256;
        if (p < P) {
            float l, h; up2(acc[i], l, h);
            out[p] = l + h + bias2;
        }
    }
}

// ---------------- launch ---------------------------------------------------
extern "C" void kernel_launch(void* const* d_in, const int* in_sizes, int n_in,
                              void* d_out, int out_size)
{
    const float* node  = (const float*)d_in[0];
    const float* edge  = (const float*)d_in[1];
    const float* hist  = (const float*)d_in[2];
    const int*   cand  = (const int*)d_in[3];
    const int*   Np    = (const int*)d_in[4];
    const float* nodeW = (const float*)d_in[5];
    const float* nodeb = (const float*)d_in[6];
    const float* edgeW = (const float*)d_in[7];
    const float* edgeb = (const float*)d_in[8];
    const float* Wih   = (const float*)d_in[9];
    const float* Whh   = (const float*)d_in[10];
    const float* bih   = (const float*)d_in[11];
    const float* bhh   = (const float*)d_in[12];
    const float* fW1   = (const float*)d_in[13];
    const float* fb1   = (const float*)d_in[14];
    const float* fW2   = (const float*)d_in[15];
    const float* fb2   = (const float*)d_in[16];

    const int Nn = in_sizes[0] / 2;
    const int Ne = in_sizes[1] / 5;
    const int T  = in_sizes[2] / 3;
    const int P  = in_sizes[3] / 2;

    static bool attr_set = false;
    if (!attr_set) {
        cudaFuncSetAttribute(k1, cudaFuncAttributeMaxDynamicSharedMemorySize, K1_SMEM);
        attr_set = true;
    }

    const int GRID1 = 148;  // block 0 = LSTM, 147 = node/edge reduce
    k1<<<GRID1, NTH, K1_SMEM>>>(node, edge, hist, Nn, Ne, T,
                                nodeW, nodeb, edgeW, edgeb, Wih, Whh, bih, bhh);
    k2<<<1, 256>>>(GRID1 - 1, Nn, Ne, fW1, fb1, fW2);
    const int g3 = (P + 2047) / 2048;
    k3<<<g3, 256>>>(cand, P, Np, fb2, (float*)d_out);
}

// round 7
// speedup vs baseline: 1.0212x; 1.0212x over previous
#include <cuda_runtime.h>
#include <cstdint>

typedef unsigned long long u64;
typedef unsigned int u32;

// ---------------- device scratch (no allocations allowed) ----------------
__device__ float g_part_edge[160][64];
__device__ float g_part_node[160][64];
__device__ float g_zhist[64];
__device__ float g_base[64];
__device__ float g_av[64];
__device__ float g_bv[64];
__device__ float g_w2v[64];

// ---------------- packed helpers ------------------------------------------
__device__ __forceinline__ u64 pk2(float a, float b) {
    u64 r; asm("mov.b64 %0,{%1,%2};" : "=l"(r) : "f"(a), "f"(b)); return r;
}
__device__ __forceinline__ void up2(u64 v, float& a, float& b) {
    asm("mov.b64 {%0,%1},%2;" : "=f"(a), "=f"(b) : "l"(v));
}
__device__ __forceinline__ u64 f2fma(u64 a, u64 b, u64 c) {
    u64 d; asm("fma.rn.f32x2 %0,%1,%2,%3;" : "=l"(d) : "l"(a), "l"(b), "l"(c)); return d;
}
__device__ __forceinline__ u64 add2(u64 a, u64 b) {
    u64 d; asm("add.rn.f32x2 %0,%1,%2;" : "=l"(d) : "l"(a), "l"(b)); return d;
}
__device__ __forceinline__ u64 relu2(u64 v) {
    u64 r;
    asm("{\n\t.reg .f32 l,h;\n\t"
        "mov.b64 {l,h}, %1;\n\t"
        "max.f32 l, l, 0f00000000;\n\t"
        "max.f32 h, h, 0f00000000;\n\t"
        "mov.b64 %0, {l,h};\n\t}"
        : "=l"(r) : "l"(v));
    return r;
}
__device__ __forceinline__ float tanh_ap(float x) {
    float r; asm("tanh.approx.f32 %0,%1;" : "=f"(r) : "f"(x)); return r;
}
__device__ __forceinline__ float sigm(float x) { return 1.f / (1.f + __expf(-x)); }

__device__ __forceinline__ u32 bfpack(float lo, float hi) {
    u32 r; asm("cvt.rn.bf16x2.f32 %0, %1, %2;" : "=r"(r) : "f"(hi), "f"(lo)); return r;
}

__device__ __forceinline__ void mma8(float& d0, float& d1, float& d2, float& d3,
                                     u32 a0, u32 a1, u32 b,
                                     float c0, float c1, float c2, float c3) {
    asm("mma.sync.aligned.m16n8k8.row.col.f32.bf16.bf16.f32 "
        "{%0,%1,%2,%3},{%4,%5},{%6},{%7,%8,%9,%10};"
        : "=f"(d0), "=f"(d1), "=f"(d2), "=f"(d3)
        : "r"(a0), "r"(a1), "r"(b), "f"(c0), "f"(c1), "f"(c2), "f"(c3));
}

#define NTH   768
#define NW    24              // warps per block
#define CH    128             // rows per warp chunk
#define REDW  68

// ---- dynamic shared layout (bytes), union of two uses --------------------
//  phase:  scratch [0, 61440)      24 warps x 640 floats (f32 chunk)
//          red     [61440, 67968)  24*68 floats
//  LSTM :  hist    [67584, 70016)  608 floats   (block 0 only; no overlap issue)
//          shh     [71040, 71552)  2 x 64 floats (double-buffered h)
#define K1_SMEM 71552

extern __shared__ __align__(16) char dsm_raw[];

// ---------------- per-warp streaming tensor-core MLP reduction ------------
// Each warp independently streams 128-row chunks (contiguous, coalesced
// LDG.128 into registers -> warp-private shared scratch). No block syncs in
// the mainloop. mma m16n8k8 bf16; bias via C operand; relu+mean in f32x2.
template<int INF>
__device__ __forceinline__ void phase(const float* __restrict__ X,
                                      const float* __restrict__ W,
                                      const float* __restrict__ bias,
                                      int nrows, float* __restrict__ partial,
                                      int nstreams, int ws)
{
    const int tid  = threadIdx.x;
    const int lane = tid & 31;
    const int w    = tid >> 5;
    const int gid  = lane >> 2;      // 0..7
    const int tig  = lane & 3;       // 0..3
    float* sw  = (float*)dsm_raw + w * 640;
    float* red = (float*)(dsm_raw + 61440);

    // B fragments (col = nt*8+gid, k = 2tig,2tig+1) + bias C (cols nt*8+2tig..+1)
    u32 bf[8];
    float c0[8], c1[8];
#pragma unroll
    for (int nt = 0; nt < 8; nt++) {
        const int ncol = nt * 8 + gid;
        const float vlo = (2 * tig < INF)     ? W[(2 * tig) * 64 + ncol]     : 0.f;
        const float vhi = (2 * tig + 1 < INF) ? W[(2 * tig + 1) * 64 + ncol] : 0.f;
        bf[nt] = bfpack(vlo, vhi);
        c0[nt] = bias[nt * 8 + 2 * tig];
        c1[nt] = bias[nt * 8 + 2 * tig + 1];
    }
    u64 acc[8] = {0, 0, 0, 0, 0, 0, 0, 0};

    const int nch = (nrows + CH - 1) / CH;
    const int nelem = nrows * INF;
    constexpr int NV = (CH * INF) / 128;    // float4 per lane per chunk
    float4 pf[NV];

    __syncthreads();   // protect scratch/red across phases

    int c = ws;
    if (c < nch) {
        const int b4 = c * (CH * INF / 4);
        if ((c + 1) * CH <= nrows) {
#pragma unroll
            for (int v = 0; v < NV; v++) pf[v] = ((const float4*)X)[b4 + lane + v * 32];
        } else {
#pragma unroll
            for (int v = 0; v < NV; v++) {
                const int e = (b4 + lane + v * 32) * 4;
                pf[v].x = (e     < nelem) ? X[e]     : 0.f;
                pf[v].y = (e + 1 < nelem) ? X[e + 1] : 0.f;
                pf[v].z = (e + 2 < nelem) ? X[e + 2] : 0.f;
                pf[v].w = (e + 3 < nelem) ? X[e + 3] : 0.f;
            }
        }
    }

    for (; c < nch; c += nstreams) {
#pragma unroll
        for (int v = 0; v < NV; v++) ((float4*)sw)[lane + v * 32] = pf[v];
        __syncwarp();

        const int cn = c + nstreams;
        if (cn < nch) {
            const int b4 = cn * (CH * INF / 4);
            if ((cn + 1) * CH <= nrows) {
#pragma unroll
                for (int v = 0; v < NV; v++) pf[v] = ((const float4*)X)[b4 + lane + v * 32];
            } else {
#pragma unroll
                for (int v = 0; v < NV; v++) {
                    const int e = (b4 + lane + v * 32) * 4;
                    pf[v].x = (e     < nelem) ? X[e]     : 0.f;
                    pf[v].y = (e + 1 < nelem) ? X[e + 1] : 0.f;
                    pf[v].z = (e + 2 < nelem) ? X[e + 2] : 0.f;
                    pf[v].w = (e + 3 < nelem) ? X[e + 3] : 0.f;
                }
            }
        }

        const int rows = min(CH, nrows - c * CH);
        if (rows == CH) {
#pragma unroll
            for (int t = 0; t < 8; t++) {
                const int r0 = t * 16 + gid;
                const float lo0 = (2 * tig < INF)     ? sw[r0 * INF + 2 * tig]           : 0.f;
                const float hi0 = (2 * tig + 1 < INF) ? sw[r0 * INF + 2 * tig + 1]       : 0.f;
                const float lo1 = (2 * tig < INF)     ? sw[(r0 + 8) * INF + 2 * tig]     : 0.f;
                const float hi1 = (2 * tig + 1 < INF) ? sw[(r0 + 8) * INF + 2 * tig + 1] : 0.f;
                const u32 a0 = bfpack(lo0, hi0);
                const u32 a1 = bfpack(lo1, hi1);
#pragma unroll
                for (int nt = 0; nt < 8; nt++) {
                    float d0, d1, d2, d3;
                    mma8(d0, d1, d2, d3, a0, a1, bf[nt], c0[nt], c1[nt], c0[nt], c1[nt]);
                    acc[nt] = add2(relu2(pk2(d0, d1)), acc[nt]);
                    acc[nt] = add2(relu2(pk2(d2, d3)), acc[nt]);
                }
            }
        } else {
#pragma unroll
            for (int t = 0; t < 8; t++) {
                const int r0 = t * 16 + gid;
                const float lo0 = (2 * tig < INF)     ? sw[r0 * INF + 2 * tig]           : 0.f;
                const float hi0 = (2 * tig + 1 < INF) ? sw[r0 * INF + 2 * tig + 1]       : 0.f;
                const float lo1 = (2 * tig < INF)     ? sw[(r0 + 8) * INF + 2 * tig]     : 0.f;
                const float hi1 = (2 * tig + 1 < INF) ? sw[(r0 + 8) * INF + 2 * tig + 1] : 0.f;
                const u32 a0 = bfpack(lo0, hi0);
                const u32 a1 = bfpack(lo1, hi1);
                const float m0 = (r0 < rows) ? 1.f : 0.f;
                const float m1 = (r0 + 8 < rows) ? 1.f : 0.f;
                const u64 m0p = pk2(m0, m0);
                const u64 m1p = pk2(m1, m1);
#pragma unroll
                for (int nt = 0; nt < 8; nt++) {
                    float d0, d1, d2, d3;
                    mma8(d0, d1, d2, d3, a0, a1, bf[nt], c0[nt], c1[nt], c0[nt], c1[nt]);
                    acc[nt] = f2fma(relu2(pk2(d0, d1)), m0p, acc[nt]);
                    acc[nt] = f2fma(relu2(pk2(d2, d3)), m1p, acc[nt]);
                }
            }
        }
        __syncwarp();
    }

    // reduce over gid (shfl xor 4,8,16), then cross-warp via shared
    __syncthreads();
#pragma unroll
    for (int nt = 0; nt < 8; nt++) {
        float lo, hi; up2(acc[nt], lo, hi);
#pragma unroll
        for (int off = 4; off <= 16; off <<= 1) {
            lo += __shfl_xor_sync(0xffffffffu, lo, off);
            hi += __shfl_xor_sync(0xffffffffu, hi, off);
        }
        if (gid == 0) {
            red[w * REDW + nt * 8 + 2 * tig]     = lo;
            red[w * REDW + nt * 8 + 2 * tig + 1] = hi;
        }
    }
    __syncthreads();
    if (tid < 64) {
        float sum = 0.f;
#pragma unroll 8
        for (int r2 = 0; r2 < NW; r2++) sum += red[r2 * REDW + tid];
        partial[tid] = sum;
    }
}

// ---------------- kernel 1: LSTM (block 0) + node/edge reduce -------------
// LSTM: 512 threads. thread = (j, gate, half):
//   j = tid>>3 (0..63), gate = (tid>>1)&3 [i,f,g,o], half = tid&1 (k-halves).
// Each thread holds 16 u64 weight regs (half a gate row, 32 k). Halves are
// combined with one shfl_xor(1); all 4 gates of j sit in the same warp, so
// the cell update is done in-warp with 3 shfls. h is double-buffered in
// shared -> ONE named barrier per timestep, zero crossbar-heavy LDS.
__global__ void __launch_bounds__(NTH, 1) k1(
    const float* __restrict__ node, const float* __restrict__ edge,
    const float* __restrict__ hist, int Nn, int Ne, int T,
    const float* __restrict__ nodeW, const float* __restrict__ nodeb,
    const float* __restrict__ edgeW, const float* __restrict__ edgeb,
    const float* __restrict__ Wih, const float* __restrict__ Whh,
    const float* __restrict__ bih, const float* __restrict__ bhh)
{
    const int tid = threadIdx.x;

    if (blockIdx.x == 0) {
        float* sh_hist = (float*)(dsm_raw + 67584);
        float* sh_h    = (float*)(dsm_raw + 71040);   // 2 x 64 floats

        for (int i = tid; i < T * 3 && i < 608; i += NTH) sh_hist[i] = hist[i];
        if (tid < 128) sh_h[tid] = 0.f;
        __syncthreads();

        if (tid < 512) {
            const int j    = tid >> 3;
            const int gate = (tid >> 1) & 3;
            const int half = tid & 1;
            const int row  = gate * 64 + j;
            const int lane = tid & 31;
            const int base = lane & 24;           // lane of (j, gate=0, half=0)

            u64 w2[16];
            const float2* wr = (const float2*)(Whh + row * 64 + half * 32);
#pragma unroll
            for (int k = 0; k < 16; k++) { float2 p = wr[k]; w2[k] = pk2(p.x, p.y); }
            const float wi0 = Wih[row * 3], wi1 = Wih[row * 3 + 1], wi2 = Wih[row * 3 + 2];
            const float bsum = bih[row] + bhh[row];
            const bool hsh = (T * 3 <= 608);
            const bool is_g = (gate == 2);
            const bool is_owner = ((tid & 7) == 0);
            float c = 0.f;

            for (int t = 0; t < T; t++) {
                const float* xp = hsh ? (sh_hist + t * 3) : (hist + t * 3);
                const float pre = fmaf(wi0, xp[0], fmaf(wi1, xp[1], fmaf(wi2, xp[2], bsum)));
                const u64* hh = (const u64*)(sh_h + (t & 1) * 64) + half * 16;
                u64 a0 = 0, a1 = 0, a2 = 0, a3 = 0;
#pragma unroll
                for (int k = 0; k < 16; k += 4) {
                    a0 = f2fma(w2[k],     hh[k],     a0);
                    a1 = f2fma(w2[k + 1], hh[k + 1], a1);
                    a2 = f2fma(w2[k + 2], hh[k + 2], a2);
                    a3 = f2fma(w2[k + 3], hh[k + 3], a3);
                }
                float s0, s1, s2, s3, s4, s5, s6, s7;
                up2(a0, s0, s1); up2(a1, s2, s3); up2(a2, s4, s5); up2(a3, s6, s7);
                float s = ((s0 + s1) + (s2 + s3)) + ((s4 + s5) + (s6 + s7));
                s += __shfl_xor_sync(0xffffffffu, s, 1);
                const float z = pre + s;
                const float a = is_g ? tanh_ap(z) : sigm(z);
                // gather the 4 gates of j at the owner lane
                const float gi = __shfl_sync(0xffffffffu, a, base + 0);
                const float gf = __shfl_sync(0xffffffffu, a, base + 2);
                const float gg = __shfl_sync(0xffffffffu, a, base + 4);
                const float go = __shfl_sync(0xffffffffu, a, base + 6);
                if (is_owner) {
                    c = fmaf(gf, c, gi * gg);
                    sh_h[((t + 1) & 1) * 64 + j] = go * tanh_ap(c);
                }
                asm volatile("bar.sync 1, 512;" ::: "memory");
            }
            if (is_owner) g_zhist[j] = sh_h[(T & 1) * 64 + j];
        }
    } else {
        const int nstreams = (gridDim.x - 1) * NW;
        const int ws = (blockIdx.x - 1) * NW + (tid >> 5);
        phase<2>(node, nodeW, nodeb, Nn, g_part_node[blockIdx.x - 1], nstreams, ws);
        phase<5>(edge, edgeW, edgeb, Ne, g_part_edge[blockIdx.x - 1], nstreams, ws);
    }
}

// ---------------- kernel 2: finalize ctx + precompute base/a/b/w2 ---------
__global__ void __launch_bounds__(256) k2(int nb, int Nn, int Ne,
                   const float* __restrict__ W1, const float* __restrict__ b1,
                   const float* __restrict__ W2f)
{
    __shared__ float ctx[192];
    __shared__ float t1[256], t2[256];
    const int tid = threadIdx.x;
    const int c = tid >> 6, j = tid & 63;

    float se = 0.f, sn = 0.f;
    for (int b = c; b < nb; b += 4) {
        se += g_part_edge[b][j];
        sn += g_part_node[b][j];
    }
    t1[tid] = se; t2[tid] = sn;
    __syncthreads();
    if (tid < 64) {
        const float e = t1[tid] + t1[tid + 64] + t1[tid + 128] + t1[tid + 192];
        const float n = t2[tid] + t2[tid + 64] + t2[tid + 128] + t2[tid + 192];
        ctx[tid]       = n * (1.f / (float)Nn);
        ctx[64 + tid]  = e * (1.f / (float)Ne);
        ctx[128 + tid] = g_zhist[tid];
    }
    __syncthreads();
    float p = 0.f;
    const int i0 = c * 48;
#pragma unroll 8
    for (int i = i0; i < i0 + 48; i++) p = fmaf(ctx[i], W1[i * 64 + j], p);
    __syncthreads();
    t1[tid] = p;
    __syncthreads();
    if (tid < 64) {
        g_base[tid] = b1[tid] + ((t1[tid] + t1[tid + 64]) + (t1[tid + 128] + t1[tid + 192]));
        g_av[tid]   = W1[192 * 64 + tid];
        g_bv[tid]   = W1[193 * 64 + tid];
        g_w2v[tid]  = W2f[tid];
    }
}

// ---------------- kernel 3: candidate scoring (ILP=8, shared wt reuse) ----
__global__ void __launch_bounds__(256) k3(const int* __restrict__ cand, int P,
                                          const int* __restrict__ Np,
                                          const float* __restrict__ fb2,
                                          float* __restrict__ out)
{
    __shared__ __align__(16) u64 s4[128];   // [jp]{base2, a2, b2, w22}
    const int tid = threadIdx.x;
    if (tid < 32) {
        s4[tid * 4 + 0] = pk2(g_base[2 * tid], g_base[2 * tid + 1]);
        s4[tid * 4 + 1] = pk2(g_av[2 * tid],   g_av[2 * tid + 1]);
        s4[tid * 4 + 2] = pk2(g_bv[2 * tid],   g_bv[2 * tid + 1]);
        s4[tid * 4 + 3] = pk2(g_w2v[2 * tid],  g_w2v[2 * tid + 1]);
    }
    const float invd = 1.f / ((float)(*Np) - 1.f + 1e-9f);
    const float bias2 = fb2[0];
    __syncthreads();

    const int p0 = blockIdx.x * 2048 + tid;
    u64 cx2[8], cy2[8];
#pragma unroll
    for (int i = 0; i < 8; i++) {
        const int p = p0 + i * 256;
        float cx = 0.f, cy = 0.f;
        if (p < P) {
            const int2 cp = ((const int2*)cand)[p];
            cx = (float)cp.x * invd;
            cy = (float)cp.y * invd;
        }
        cx2[i] = pk2(cx, cx);
        cy2[i] = pk2(cy, cy);
    }

    u64 acc[8] = {0, 0, 0, 0, 0, 0, 0, 0};
#pragma unroll 8
    for (int jp = 0; jp < 32; jp++) {
        const u64 bb = s4[jp * 4 + 0];
        const u64 aa = s4[jp * 4 + 1];
        const u64 bv = s4[jp * 4 + 2];
        const u64 ww = s4[jp * 4 + 3];
#pragma unroll
        for (int i = 0; i < 8; i++) {
            u64 tt = f2fma(cx2[i], aa, bb);
            tt = f2fma(cy2[i], bv, tt);
            acc[i] = f2fma(relu2(tt), ww, acc[i]);
        }
    }
#pragma unroll
    for (int i = 0; i < 8; i++) {
        const int p = p0 + i * 256;
        if (p < P) {
            float l, h; up2(acc[i], l, h);
            out[p] = l + h + bias2;
        }
    }
}

// ---------------- launch ---------------------------------------------------
extern "C" void kernel_launch(void* const* d_in, const int* in_sizes, int n_in,
                              void* d_out, int out_size)
{
    const float* node  = (const float*)d_in[0];
    const float* edge  = (const float*)d_in[1];
    const float* hist  = (const float*)d_in[2];
    const int*   cand  = (const int*)d_in[3];
    const int*   Np    = (const int*)d_in[4];
    const float* nodeW = (const float*)d_in[5];
    const float* nodeb = (const float*)d_in[6];
    const float* edgeW = (const float*)d_in[7];
    const float* edgeb = (const float*)d_in[8];
    const float* Wih   = (const float*)d_in[9];
    const float* Whh   = (const float*)d_in[10];
    const float* bih   = (const float*)d_in[11];
    const float* bhh   = (const float*)d_in[12];
    const float* fW1   = (const float*)d_in[13];
    const float* fb1   = (const float*)d_in[14];
    const float* fW2   = (const float*)d_in[15];
    const float* fb2   = (const float*)d_in[16];

    const int Nn = in_sizes[0] / 2;
    const int Ne = in_sizes[1] / 5;
    const int T  = in_sizes[2] / 3;
    const int P  = in_sizes[3] / 2;

    static bool attr_set = false;
    if (!attr_set) {
        cudaFuncSetAttribute(k1, cudaFuncAttributeMaxDynamicSharedMemorySize, K1_SMEM);
        attr_set = true;
    }

    const int GRID1 = 148;  // block 0 = LSTM, 147 = node/edge reduce
    k1<<<GRID1, NTH, K1_SMEM>>>(node, edge, hist, Nn, Ne, T,
                                nodeW, nodeb, edgeW, edgeb, Wih, Whh, bih, bhh);
    k2<<<1, 256>>>(GRID1 - 1, Nn, Ne, fW1, fb1, fW2);
    const int g3 = (P + 2047) / 2048;
    k3<<<g3, 256>>>(cand, P, Np, fb2, (float*)d_out);
}